// round 15
// baseline (speedup 1.0000x reference)
#include <cuda_runtime.h>
#include <math.h>
#include <stdint.h>

// Problem constants (LMUCell: B=32, T=2048, D=128, U=512, N=256)
#define Bsz  32
#define Tn   2048
#define Dn   128
#define Un   512
#define Nn   256
#define KTOT 896     // D + U + N  (fused input length)
#define OTOT 768     // U + N      (fused output length)
#define GRID 128     // persistent CTAs: 4 batch-groups x 32 column-groups
#define TPB  256
#define COLS_CTA  24
#define PAIRS_CTA 12
#define SMEM_W_BYTES (PAIRS_CTA * KTOT * 8)   // 86016 B dynamic smem

// ---------------- device scratch (static, no allocation) ----------------
__device__ float g_W1[Nn * Un];                     // (I+AT) @ Wmh
__device__ float g_w2[Un];                          // BT @ Wmh
__device__ float g_WT[OTOT * KTOT];                 // WbigT[u][k]  (k contiguous)
// splatted state: [buf][bq][k(768)][b(4)] as (v,v) u64 pairs
__device__ __align__(16) unsigned long long g_state[2][8 * OTOT * 4];
// splatted x: [b][t][k] as (v,v) u64
__device__ unsigned long long g_xs[(size_t)Bsz * Tn * Dn];   // 64 MB
__device__ unsigned g_arrive[GRID * 32];            // per-CTA flags, 128B apart

// ---------------- f32x2 helpers ----------------
__device__ __forceinline__ unsigned long long splat2(float a) {
    unsigned long long r; unsigned au = __float_as_uint(a);
    asm("mov.b64 %0,{%1,%1};" : "=l"(r) : "r"(au));
    return r;
}
__device__ __forceinline__ void fma2(unsigned long long& d, unsigned long long a, unsigned long long b) {
    asm("fma.rn.f32x2 %0,%1,%2,%0;" : "+l"(d) : "l"(a), "l"(b));
}
__device__ __forceinline__ unsigned long long add2(unsigned long long a, unsigned long long b) {
    unsigned long long r;
    asm("add.rn.f32x2 %0,%1,%2;" : "=l"(r) : "l"(a), "l"(b));
    return r;
}
__device__ __forceinline__ void unpack2(unsigned long long v, float& lo, float& hi) {
    unsigned a, b;
    asm("mov.b64 {%0,%1},%2;" : "=r"(a), "=r"(b) : "l"(v));
    lo = __uint_as_float(a); hi = __uint_as_float(b);
}

// ---------------- init0: pre-splat x into u64 (v,v) pairs ----------------
__global__ void lmu_init0(const float* __restrict__ x) {
    size_t i = (size_t)blockIdx.x * blockDim.x + threadIdx.x;
    if (i < (size_t)Bsz * Tn * Dn) g_xs[i] = splat2(x[i]);
}

// ---------------- init1: W1, w2, splatted state init, flag reset ----------------
__global__ void lmu_init1(const float* __restrict__ h0, const float* __restrict__ m0,
                          const float* __restrict__ Wmh, const float* __restrict__ AT,
                          const float* __restrict__ BT) {
    int i = blockIdx.x * blockDim.x + threadIdx.x;
    const int b1 = Nn * Un;
    const int b2 = b1 + Un;
    const int b3 = b2 + 8 * OTOT * 4;
    if (i < b1) {
        int j = i / Un, u = i % Un;
        float s = 0.f;
        #pragma unroll 4
        for (int q = 0; q < Nn; q++) {
            float a = AT[j * Nn + q] + (q == j ? 1.0f : 0.0f);
            s = fmaf(a, Wmh[q * Un + u], s);
        }
        g_W1[i] = s;
    } else if (i < b2) {
        int u = i - b1;
        float s = 0.f;
        #pragma unroll 4
        for (int q = 0; q < Nn; q++) s = fmaf(BT[q], Wmh[q * Un + u], s);
        g_w2[u] = s;
    } else if (i < b3) {
        int r = i - b2;
        int b  = r & 3;
        int k  = (r >> 2) % OTOT;
        int bq = r / (OTOT * 4);
        int gb = bq * 4 + b;
        float v = (k < Un) ? h0[gb * Un + k] : m0[gb * Nn + (k - Un)];
        g_state[0][r] = splat2(v);
    } else if (i < b3 + GRID) {
        g_arrive[(i - b3) * 32] = 0u;   // reset barrier flags (graph replays!)
    }
}

// ---------------- init2: build fused WbigT[u][k] ----------------
// z[b][u] = sum_k act[k] * WbigT[u][k],  act = [x_t(128) | h(512) | m(256)]
__global__ void lmu_init2(const float* __restrict__ ie, const float* __restrict__ he,
                          const float* __restrict__ me, const float* __restrict__ Wi,
                          const float* __restrict__ Whh, const float* __restrict__ AT,
                          const float* __restrict__ BT) {
    int i = blockIdx.x * blockDim.x + threadIdx.x;
    if (i >= OTOT * KTOT) return;
    int u = i / KTOT, k = i % KTOT;
    float v;
    if (u < Un) {                                   // h-output columns
        float w2u = g_w2[u];
        if (k < Dn)            v = fmaf(ie[k], w2u, Wi[k * Un + u]);
        else if (k < Dn + Un) { int kk = k - Dn; v = fmaf(he[kk], w2u, Whh[kk * Un + u]); }
        else                  { int j  = k - Dn - Un; v = fmaf(me[j], w2u, g_W1[j * Un + u]); }
    } else {                                        // m-output columns
        int n = u - Un; float btn = BT[n];
        if (k < Dn)            v = ie[k] * btn;
        else if (k < Dn + Un)  v = he[k - Dn] * btn;
        else { int j = k - Dn - Un; v = AT[j * Nn + n] + (j == n ? 1.0f : 0.0f) + me[j] * btn; }
    }
    g_WT[i] = v;
}

// ---------------- main persistent recurrence kernel ----------------
extern __shared__ unsigned long long sW[];          // 12 pairs x 896 k (86 KB)

__global__ void __launch_bounds__(TPB, 1) lmu_main(float* __restrict__ out) {
    const int tid = threadIdx.x;
    const int c   = blockIdx.x;
    const int cg  = c & 31;               // column group 0..31
    const int bg  = c >> 5;               // batch group 0..3
    const int obase = cg * COLS_CTA;

    // Load this CTA's 24 weight columns as 12 packed (w0,w1) pairs into SMEM.
    for (int idx = tid; idx < PAIRS_CTA * KTOT; idx += TPB) {
        int pp = idx / KTOT, k = idx % KTOT;
        unsigned w0 = __float_as_uint(g_WT[(obase + 2 * pp)     * KTOT + k]);
        unsigned w1 = __float_as_uint(g_WT[(obase + 2 * pp + 1) * KTOT + k]);
        unsigned long long pk;
        asm("mov.b64 %0,{%1,%2};" : "=l"(pk) : "r"(w0), "r"(w1));
        sW[idx] = pk;
    }
    __syncthreads();

    const int warp = tid >> 5, lane = tid & 31;
    const int pb  = warp >> 1;            // pair-block 0..3 (3 pairs each)
    const int bq  = warp & 1;             // local batch quad
    const int gbq = bg * 2 + bq;          // global batch quad 0..7
    const unsigned long long* xb = g_xs + (size_t)(gbq * 4) * (Tn * Dn);
    const unsigned long long* wp = &sW[(pb * 3) * KTOT];

    // Prefetch splatted x for t = 0
    unsigned long long xr[16];
    #pragma unroll
    for (int j = 0; j < 4; j++) {
        int k = lane + 32 * j;
        #pragma unroll
        for (int b = 0; b < 4; b++)
            xr[j * 4 + b] = xb[((size_t)b * Tn) * Dn + k];
    }

    for (int t = 0; t < Tn; t++) {
        const unsigned long long* st = &g_state[t & 1][gbq * OTOT * 4];

        unsigned long long acc[3][4];
        #pragma unroll
        for (int p = 0; p < 3; p++)
            #pragma unroll
            for (int b = 0; b < 4; b++) acc[p][b] = 0ull;

        // ---- x part (prefetched, pre-splatted): k = lane + 32j, j = 0..3 ----
        #pragma unroll
        for (int j = 0; j < 4; j++) {
            int k = lane + 32 * j;
            #pragma unroll
            for (int p = 0; p < 3; p++) {
                unsigned long long w = wp[p * KTOT + k];
                fma2(acc[p][0], xr[j * 4 + 0], w);
                fma2(acc[p][1], xr[j * 4 + 1], w);
                fma2(acc[p][2], xr[j * 4 + 2], w);
                fma2(acc[p][3], xr[j * 4 + 3], w);
            }
        }

        // ---- state part (pre-splatted): s = lane + 32j, j = 0..23 ----
        #pragma unroll 8
        for (int j = 0; j < 24; j++) {
            int s = lane + 32 * j;
            ulonglong2 a01 = *(const ulonglong2*)&st[s * 4];
            ulonglong2 a23 = *(const ulonglong2*)&st[s * 4 + 2];
            #pragma unroll
            for (int p = 0; p < 3; p++) {
                unsigned long long w = wp[p * KTOT + Dn + s];
                fma2(acc[p][0], a01.x, w); fma2(acc[p][1], a01.y, w);
                fma2(acc[p][2], a23.x, w); fma2(acc[p][3], a23.y, w);
            }
        }

        // ---- reduce partials across 32 lanes (k-split) ----
        #pragma unroll
        for (int m = 16; m; m >>= 1) {
            #pragma unroll
            for (int p = 0; p < 3; p++)
                #pragma unroll
                for (int b = 0; b < 4; b++)
                    acc[p][b] = add2(acc[p][b], __shfl_xor_sync(0xffffffffu, acc[p][b], m));
        }

        // ---- write new splatted state (lanes 0..11: (pair, batch)) ----
        unsigned long long* stout = &g_state[(t + 1) & 1][gbq * OTOT * 4];
        float v0 = 0.f, v1 = 0.f;
        int o0 = 0;
        bool isH = false;
        if (lane < 12) {
            int p = lane >> 2, b = lane & 3;
            unpack2(acc[p][b], v0, v1);
            o0 = obase + (pb * 3 + p) * 2;      // even; pairs never straddle u=512
            isH = (o0 < Un);
            if (isH) { v0 = tanhf(v0); v1 = tanhf(v1); }
            stout[o0 * 4 + b]       = splat2(v0);
            stout[(o0 + 1) * 4 + b] = splat2(v1);
        }

        // ---- arrive: state writes visible, then per-bg flag (release) ----
        __syncthreads();
        if (tid == 0) {
            asm volatile("st.global.release.gpu.u32 [%0], %1;"
                         :: "l"(&g_arrive[c * 32]), "r"((unsigned)(t + 1)) : "memory");
        }

        // ---- hide latency behind the barrier: prefetch x(t+1), write out ----
        int tn = (t + 1 < Tn) ? (t + 1) : t;
        #pragma unroll
        for (int j = 0; j < 4; j++) {
            int k = lane + 32 * j;
            #pragma unroll
            for (int b = 0; b < 4; b++)
                xr[j * 4 + b] = xb[((size_t)b * Tn + tn) * Dn + k];
        }
        if (isH) {
            int b = lane & 3;
            size_t base = ((size_t)(gbq * 4 + b) * Tn + t) * Un;
            out[base + o0]     = v0;
            out[base + o0 + 1] = v1;
        }

        // ---- wait: the 32 CTAs of THIS batch-group only ----
        if (t + 1 < Tn) {
            if (tid < 32) {
                const unsigned* fp = &g_arrive[(bg * 32 + tid) * 32];
                unsigned v;
                do {
                    asm volatile("ld.global.acquire.gpu.u32 %0, [%1];" : "=r"(v) : "l"(fp));
                } while (v < (unsigned)(t + 1));
            }
            __syncthreads();
        }
    }
}

// ---------------- launch ----------------
extern "C" void kernel_launch(void* const* d_in, const int* in_sizes, int n_in,
                              void* d_out, int out_size) {
    const float* x   = (const float*)d_in[0];   // (32,2048,128)
    const float* h0  = (const float*)d_in[1];   // (32,512)
    const float* m0  = (const float*)d_in[2];   // (32,256)
    const float* ie  = (const float*)d_in[3];   // (128,1)
    const float* he  = (const float*)d_in[4];   // (512,1)
    const float* me  = (const float*)d_in[5];   // (256,1)
    const float* Wi  = (const float*)d_in[6];   // (128,512)
    const float* Whh = (const float*)d_in[7];   // (512,512)
    const float* Wmh = (const float*)d_in[8];   // (256,512)
    const float* AT  = (const float*)d_in[9];   // (256,256)
    const float* BT  = (const float*)d_in[10];  // (1,256)
    float* out = (float*)d_out;                 // (32,2048,512)

    cudaFuncSetAttribute(lmu_main, cudaFuncAttributeMaxDynamicSharedMemorySize,
                         SMEM_W_BYTES);

    // init0: pre-splat x (8.4M elements)
    size_t nx = (size_t)Bsz * Tn * Dn;
    lmu_init0<<<(unsigned)((nx + TPB - 1) / TPB), TPB>>>(x);

    // init1: W1 = (I+AT)@Wmh, w2 = BT@Wmh, splatted state[0], flags reset
    int n1 = Nn * Un + Un + 8 * OTOT * 4 + GRID;
    lmu_init1<<<(n1 + TPB - 1) / TPB, TPB>>>(h0, m0, Wmh, AT, BT);

    // init2: fused big weight matrix (transposed, k-contiguous rows)
    int n2 = OTOT * KTOT;
    lmu_init2<<<(n2 + TPB - 1) / TPB, TPB>>>(ie, he, me, Wi, Whh, AT, BT);

    // persistent recurrence
    lmu_main<<<GRID, TPB, SMEM_W_BYTES>>>(out);
}

// round 16
// speedup vs baseline: 1.2257x; 1.2257x over previous
#include <cuda_runtime.h>
#include <math.h>
#include <stdint.h>

// Problem constants (LMUCell: B=32, T=2048, D=128, U=512, N=256)
#define Bsz  32
#define Tn   2048
#define Dn   128
#define Un   512
#define Nn   256
#define KTOT 896     // D + U + N
#define OTOT 768     // U + N
#define GRID 128     // 32 column-groups x 4 batch-groups
#define TPB  256     // 8 warps = 4 pair-blocks x 2 k-halves
#define SMEM_W_BYTES (12 * KTOT * 8)   // 86016 B dynamic smem

typedef unsigned long long u64t;

// ---------------- device scratch (static, no allocation) ----------------
__device__ float g_W1[Nn * Un];                    // (I+AT) @ Wmh
__device__ float g_w2[Un];                         // BT @ Wmh
__device__ float g_WT[OTOT * KTOT];                // WbigT[u][k]
// state: [buf][bg(4)][k(768)][b(8)] plain float
__device__ __align__(16) float g_state[2][4 * OTOT * 8];
// x transposed: [bg(4)][t][k(128)][b(8)]
__device__ __align__(16) float g_xt[(size_t)4 * Tn * Dn * 8];   // 33 MB
__device__ unsigned g_arrive[GRID * 32];           // per-CTA flags, 128B apart

// ---------------- f32x2 helpers ----------------
__device__ __forceinline__ u64t splat2(float a) {
    u64t r; unsigned au = __float_as_uint(a);
    asm("mov.b64 %0,{%1,%1};" : "=l"(r) : "r"(au));
    return r;
}
__device__ __forceinline__ void fma2(u64t& d, u64t a, u64t b) {
    asm("fma.rn.f32x2 %0,%1,%2,%0;" : "+l"(d) : "l"(a), "l"(b));
}
__device__ __forceinline__ u64t add2(u64t a, u64t b) {
    u64t r;
    asm("add.rn.f32x2 %0,%1,%2;" : "=l"(r) : "l"(a), "l"(b));
    return r;
}
__device__ __forceinline__ void unpack2(u64t v, float& lo, float& hi) {
    unsigned a, b;
    asm("mov.b64 {%0,%1},%2;" : "=r"(a), "=r"(b) : "l"(v));
    lo = __uint_as_float(a); hi = __uint_as_float(b);
}

// ---------------- init0: transpose x -> [bg][t][k][b8] ----------------
__global__ void lmu_init0(const float* __restrict__ x) {
    size_t i = (size_t)blockIdx.x * blockDim.x + threadIdx.x;
    if (i >= (size_t)4 * Tn * Dn * 8) return;
    int b  = (int)(i & 7);
    int k  = (int)((i >> 3) & 127);
    int t  = (int)((i >> 10) & 2047);
    int bg = (int)(i >> 21);
    g_xt[i] = x[((size_t)(bg * 8 + b) * Tn + t) * Dn + k];
}

// ---------------- init1: W1, w2, state init, flag reset ----------------
__global__ void lmu_init1(const float* __restrict__ h0, const float* __restrict__ m0,
                          const float* __restrict__ Wmh, const float* __restrict__ AT,
                          const float* __restrict__ BT) {
    int i = blockIdx.x * blockDim.x + threadIdx.x;
    const int b1 = Nn * Un;
    const int b2 = b1 + Un;
    const int b3 = b2 + 4 * OTOT * 8;
    if (i < b1) {
        int j = i / Un, u = i % Un;
        float s = 0.f;
        #pragma unroll 4
        for (int q = 0; q < Nn; q++) {
            float a = AT[j * Nn + q] + (q == j ? 1.0f : 0.0f);
            s = fmaf(a, Wmh[q * Un + u], s);
        }
        g_W1[i] = s;
    } else if (i < b2) {
        int u = i - b1;
        float s = 0.f;
        #pragma unroll 4
        for (int q = 0; q < Nn; q++) s = fmaf(BT[q], Wmh[q * Un + u], s);
        g_w2[u] = s;
    } else if (i < b3) {
        int r  = i - b2;
        int b  = r & 7;
        int k  = (r >> 3) % OTOT;
        int bg = r / (OTOT * 8);
        int gb = bg * 8 + b;
        g_state[0][r] = (k < Un) ? h0[gb * Un + k] : m0[gb * Nn + (k - Un)];
    } else if (i < b3 + GRID) {
        g_arrive[(i - b3) * 32] = 0u;   // reset barrier flags (graph replays!)
    }
}

// ---------------- init2: build fused WbigT[u][k] ----------------
// z[b][u] = sum_k act[k] * WbigT[u][k],  act = [x_t(128) | h(512) | m(256)]
__global__ void lmu_init2(const float* __restrict__ ie, const float* __restrict__ he,
                          const float* __restrict__ me, const float* __restrict__ Wi,
                          const float* __restrict__ Whh, const float* __restrict__ AT,
                          const float* __restrict__ BT) {
    int i = blockIdx.x * blockDim.x + threadIdx.x;
    if (i >= OTOT * KTOT) return;
    int u = i / KTOT, k = i % KTOT;
    float v;
    if (u < Un) {
        float w2u = g_w2[u];
        if (k < Dn)            v = fmaf(ie[k], w2u, Wi[k * Un + u]);
        else if (k < Dn + Un) { int kk = k - Dn; v = fmaf(he[kk], w2u, Whh[kk * Un + u]); }
        else                  { int j  = k - Dn - Un; v = fmaf(me[j], w2u, g_W1[j * Un + u]); }
    } else {
        int n = u - Un; float btn = BT[n];
        if (k < Dn)            v = ie[k] * btn;
        else if (k < Dn + Un)  v = he[k - Dn] * btn;
        else { int j = k - Dn - Un; v = AT[j * Nn + n] + (j == n ? 1.0f : 0.0f) + me[j] * btn; }
    }
    g_WT[i] = v;
}

// ---------------- main persistent recurrence kernel ----------------
extern __shared__ u64t sW[];                        // [12 pairs][896 k] (86 KB)

__global__ void __launch_bounds__(TPB, 1) lmu_main(float* __restrict__ out) {
    __shared__ u64t sRed[96];                       // [pb4][p3*8+b8] kh0 partials

    const int tid = threadIdx.x, c = blockIdx.x;
    const int cg = c & 31, bg = c >> 5;
    const int obase = cg * 24;

    // Load this CTA's 24 weight columns as 12 (w0,w1) u64 pairs into SMEM.
    for (int idx = tid; idx < 12 * KTOT; idx += TPB) {
        int pp = idx / KTOT, k = idx % KTOT;
        unsigned w0 = __float_as_uint(g_WT[(obase + 2 * pp)     * KTOT + k]);
        unsigned w1 = __float_as_uint(g_WT[(obase + 2 * pp + 1) * KTOT + k]);
        u64t pk;
        asm("mov.b64 %0,{%1,%2};" : "=l"(pk) : "r"(w0), "r"(w1));
        sW[idx] = pk;
    }
    __syncthreads();

    const int warp = tid >> 5, lane = tid & 31;
    const int pb = warp >> 1;        // pair-block 0..3 (3 pairs each)
    const int kh = warp & 1;         // k-half: 0 -> [0,448), 1 -> [448,896)
    const u64t* wp = &sW[(pb * 3) * KTOT];
    const float* xtb = g_xt + (size_t)bg * Tn * Dn * 8;

    // Prefetch x(t=0) for kh0 warps: 4 j x 8 batches
    float xr[4][8];
    if (kh == 0) {
        #pragma unroll
        for (int j = 0; j < 4; j++) {
            const float4* xp = (const float4*)&xtb[(size_t)(j * 32 + lane) * 8];
            float4 a = __ldg(xp), b = __ldg(xp + 1);
            xr[j][0]=a.x; xr[j][1]=a.y; xr[j][2]=a.z; xr[j][3]=a.w;
            xr[j][4]=b.x; xr[j][5]=b.y; xr[j][6]=b.z; xr[j][7]=b.w;
        }
    }

    for (int t = 0; t < Tn; t++) {
        const float* st = &g_state[t & 1][bg * OTOT * 8];

        u64t acc[3][8];
        #pragma unroll
        for (int p = 0; p < 3; p++)
            #pragma unroll
            for (int b = 0; b < 8; b++) acc[p][b] = 0ull;

        if (kh == 0) {
            // ---- x part: k = lane + 32j, j = 0..3 (prefetched) ----
            #pragma unroll
            for (int j = 0; j < 4; j++) {
                int k = j * 32 + lane;
                u64t w0 = wp[k], w1 = wp[KTOT + k], w2 = wp[2 * KTOT + k];
                #pragma unroll
                for (int b = 0; b < 8; b++) {
                    u64t a = splat2(xr[j][b]);
                    fma2(acc[0][b], a, w0); fma2(acc[1][b], a, w1); fma2(acc[2][b], a, w2);
                }
            }
            // ---- state k = 128..447: j = 0..9 ----
            #pragma unroll
            for (int j = 0; j < 10; j++) {
                int sk = j * 32 + lane;            // state idx; weight k = 128+sk
                const float4* sp = (const float4*)&st[sk * 8];
                float4 a = __ldcg(sp), b4 = __ldcg(sp + 1);
                int k = 128 + sk;
                u64t w0 = wp[k], w1 = wp[KTOT + k], w2 = wp[2 * KTOT + k];
                float av[8] = {a.x, a.y, a.z, a.w, b4.x, b4.y, b4.z, b4.w};
                #pragma unroll
                for (int b = 0; b < 8; b++) {
                    u64t aa = splat2(av[b]);
                    fma2(acc[0][b], aa, w0); fma2(acc[1][b], aa, w1); fma2(acc[2][b], aa, w2);
                }
            }
        } else {
            // ---- state k = 448..895: j = 0..13 ----
            #pragma unroll
            for (int j = 0; j < 14; j++) {
                int sk = 320 + j * 32 + lane;
                const float4* sp = (const float4*)&st[sk * 8];
                float4 a = __ldcg(sp), b4 = __ldcg(sp + 1);
                int k = 128 + sk;
                u64t w0 = wp[k], w1 = wp[KTOT + k], w2 = wp[2 * KTOT + k];
                float av[8] = {a.x, a.y, a.z, a.w, b4.x, b4.y, b4.z, b4.w};
                #pragma unroll
                for (int b = 0; b < 8; b++) {
                    u64t aa = splat2(av[b]);
                    fma2(acc[0][b], aa, w0); fma2(acc[1][b], aa, w1); fma2(acc[2][b], aa, w2);
                }
            }
        }

        // ---- reduce: level0 xor16 exchanges batch-halves (24 -> 12 live) ----
        u64t r[3][4];
        const bool hi = (lane & 16) != 0;
        #pragma unroll
        for (int p = 0; p < 3; p++)
            #pragma unroll
            for (int b = 0; b < 4; b++) {
                u64t t0 = __shfl_xor_sync(0xffffffffu, acc[p][b],     16);
                u64t t1 = __shfl_xor_sync(0xffffffffu, acc[p][b + 4], 16);
                r[p][b] = hi ? add2(acc[p][b + 4], t1) : add2(acc[p][b], t0);
            }
        #pragma unroll
        for (int m = 8; m; m >>= 1)
            #pragma unroll
            for (int p = 0; p < 3; p++)
                #pragma unroll
                for (int b = 0; b < 4; b++)
                    r[p][b] = add2(r[p][b], __shfl_xor_sync(0xffffffffu, r[p][b], m));

        // ---- each half-group lane selects its (p, b) value ----
        const int lid   = lane & 15;
        const int p_    = lid >> 2, b4_ = lid & 3;
        const int bglob = (hi ? 4 : 0) + b4_;
        const bool active = lid < 12;
        u64t mine = 0ull;
        if (active) {
            u64t rp0 = b4_==0 ? r[0][0] : b4_==1 ? r[0][1] : b4_==2 ? r[0][2] : r[0][3];
            u64t rp1 = b4_==0 ? r[1][0] : b4_==1 ? r[1][1] : b4_==2 ? r[1][2] : r[1][3];
            u64t rp2 = b4_==0 ? r[2][0] : b4_==1 ? r[2][1] : b4_==2 ? r[2][2] : r[2][3];
            mine = p_==0 ? rp0 : p_==1 ? rp1 : rp2;
        }
        const int ridx = pb * 24 + p_ * 8 + bglob;
        if (kh == 0 && active) sRed[ridx] = mine;
        __syncthreads();                                    // A: partials visible

        float v0 = 0.f, v1 = 0.f; int o0 = 0; bool isH = false;
        float* stn = &g_state[(t + 1) & 1][bg * OTOT * 8];
        if (kh == 1 && active) {
            u64t s = add2(mine, sRed[ridx]);
            unpack2(s, v0, v1);
            o0 = obase + (pb * 3 + p_) * 2;                 // even; no 512-straddle
            isH = (o0 < Un);
            if (isH) { v0 = tanhf(v0); v1 = tanhf(v1); }
            stn[o0 * 8 + bglob]       = v0;
            stn[(o0 + 1) * 8 + bglob] = v1;
        }
        __syncthreads();                                    // B: state stores done
        if (tid == 0) {
            asm volatile("st.global.release.gpu.u32 [%0], %1;"
                         :: "l"(&g_arrive[c * 32]), "r"((unsigned)(t + 1)) : "memory");
        }

        // ---- hidden behind barrier: kh0 prefetch x(t+1); kh1 out stores ----
        int tn1 = (t + 1 < Tn) ? (t + 1) : t;
        if (kh == 0) {
            #pragma unroll
            for (int j = 0; j < 4; j++) {
                const float4* xp = (const float4*)
                    &xtb[((size_t)tn1 * Dn + (j * 32 + lane)) * 8];
                float4 a = __ldg(xp), b = __ldg(xp + 1);
                xr[j][0]=a.x; xr[j][1]=a.y; xr[j][2]=a.z; xr[j][3]=a.w;
                xr[j][4]=b.x; xr[j][5]=b.y; xr[j][6]=b.z; xr[j][7]=b.w;
            }
        } else if (isH) {
            size_t ob = ((size_t)(bg * 8 + bglob) * Tn + t) * Un + o0;
            *(float2*)&out[ob] = make_float2(v0, v1);
        }

        // ---- wait: the 32 CTAs of THIS batch-group ----
        if (t + 1 < Tn) {
            if (tid < 32) {
                const unsigned* fp = &g_arrive[(bg * 32 + tid) * 32];
                unsigned v;
                do {
                    asm volatile("ld.global.acquire.gpu.u32 %0,[%1];" : "=r"(v) : "l"(fp));
                } while (v < (unsigned)(t + 1));
            }
            __syncthreads();                                // C
        }
    }
}

// ---------------- launch ----------------
extern "C" void kernel_launch(void* const* d_in, const int* in_sizes, int n_in,
                              void* d_out, int out_size) {
    const float* x   = (const float*)d_in[0];   // (32,2048,128)
    const float* h0  = (const float*)d_in[1];   // (32,512)
    const float* m0  = (const float*)d_in[2];   // (32,256)
    const float* ie  = (const float*)d_in[3];   // (128,1)
    const float* he  = (const float*)d_in[4];   // (512,1)
    const float* me  = (const float*)d_in[5];   // (256,1)
    const float* Wi  = (const float*)d_in[6];   // (128,512)
    const float* Whh = (const float*)d_in[7];   // (512,512)
    const float* Wmh = (const float*)d_in[8];   // (256,512)
    const float* AT  = (const float*)d_in[9];   // (256,256)
    const float* BT  = (const float*)d_in[10];  // (1,256)
    float* out = (float*)d_out;                 // (32,2048,512)

    cudaFuncSetAttribute(lmu_main, cudaFuncAttributeMaxDynamicSharedMemorySize,
                         SMEM_W_BYTES);

    // init0: transpose x to [bg][t][k][b8]
    size_t nx = (size_t)4 * Tn * Dn * 8;
    lmu_init0<<<(unsigned)((nx + TPB - 1) / TPB), TPB>>>(x);

    // init1: W1, w2, state[0] (new layout), flags reset
    int n1 = Nn * Un + Un + 4 * OTOT * 8 + GRID;
    lmu_init1<<<(n1 + TPB - 1) / TPB, TPB>>>(h0, m0, Wmh, AT, BT);

    // init2: fused big weight matrix
    int n2 = OTOT * KTOT;
    lmu_init2<<<(n2 + TPB - 1) / TPB, TPB>>>(ie, he, me, Wi, Whh, AT, BT);

    // persistent recurrence
    lmu_main<<<GRID, TPB, SMEM_W_BYTES>>>(out);
}